// round 1
// baseline (speedup 1.0000x reference)
#include <cuda_runtime.h>
#include <math.h>

#define B_ 2
#define S_ 4096
#define E_ 1024
#define D_ 64          // QD == VD == 64
#define WIN_ 5
#define DIL_ 2

// Scratch (allocation-free rule: __device__ globals)
__device__ float g_Q[B_ * S_ * D_];
__device__ float g_K[B_ * S_ * D_];
__device__ float g_V[B_ * S_ * D_];
__device__ float g_Vsum[B_ * D_];

// ---------------------------------------------------------------------------
// Kernel 1: QKV projection GEMM.
// C[8192 x 64] = x[8192 x 1024] @ W[1024 x 64] + bias, for W in {Wq, Wk, Wv}
// selected by blockIdx.y. Classic SMEM-tiled fp32: BM=64, BN=64, BK=16,
// 256 threads, 4x4 micro-tile per thread.
// ---------------------------------------------------------------------------
#define BM 64
#define BN 64
#define BK 16

__global__ __launch_bounds__(256) void qkv_gemm(
    const float* __restrict__ x,
    const float* __restrict__ Wq, const float* __restrict__ bq,
    const float* __restrict__ Wk, const float* __restrict__ bk,
    const float* __restrict__ Wv, const float* __restrict__ bv)
{
    const float* W;
    const float* bias;
    float* out;
    if (blockIdx.y == 0)      { W = Wq; bias = bq; out = g_Q; }
    else if (blockIdx.y == 1) { W = Wk; bias = bk; out = g_K; }
    else                      { W = Wv; bias = bv; out = g_V; }

    __shared__ float As[BK][BM + 4];   // transposed A tile, padded
    __shared__ float Bs[BK][BN];

    const int tid = threadIdx.x;
    const int rowBase = blockIdx.x * BM;

    // compute micro-tile coords
    const int ty = tid >> 4;        // 0..15 -> rows ty*4..ty*4+3
    const int tx = tid & 15;        // 0..15 -> cols tx*4..tx*4+3

    // A load: 64 rows x 16 cols = 256 float4 along K
    const int am  = tid >> 2;           // row within tile 0..63
    const int ak4 = (tid & 3) * 4;      // k offset 0,4,8,12
    // B load: 16 rows x 64 cols = 256 float4 along N
    const int bkr = tid >> 4;           // k-row 0..15
    const int bn4 = (tid & 15) * 4;     // n offset

    float acc[4][4];
#pragma unroll
    for (int i = 0; i < 4; i++)
#pragma unroll
        for (int j = 0; j < 4; j++) acc[i][j] = 0.f;

    const float* xrow = x + (size_t)(rowBase + am) * E_;

    for (int kt = 0; kt < E_; kt += BK) {
        float4 a = *(const float4*)&xrow[kt + ak4];
        As[ak4 + 0][am] = a.x;
        As[ak4 + 1][am] = a.y;
        As[ak4 + 2][am] = a.z;
        As[ak4 + 3][am] = a.w;

        float4 bv4 = *(const float4*)&W[(size_t)(kt + bkr) * D_ + bn4];
        *(float4*)&Bs[bkr][bn4] = bv4;

        __syncthreads();

#pragma unroll
        for (int kk = 0; kk < BK; kk++) {
            float ar[4], br[4];
#pragma unroll
            for (int i = 0; i < 4; i++) ar[i] = As[kk][ty * 4 + i];
#pragma unroll
            for (int j = 0; j < 4; j++) br[j] = Bs[kk][tx * 4 + j];
#pragma unroll
            for (int i = 0; i < 4; i++)
#pragma unroll
                for (int j = 0; j < 4; j++) acc[i][j] = fmaf(ar[i], br[j], acc[i][j]);
        }
        __syncthreads();
    }

#pragma unroll
    for (int i = 0; i < 4; i++) {
        int r = rowBase + ty * 4 + i;
#pragma unroll
        for (int j = 0; j < 4; j++) {
            int c = tx * 4 + j;
            out[(size_t)r * D_ + c] = acc[i][j] + bias[c];
        }
    }
}

// ---------------------------------------------------------------------------
// Kernel 2: per-batch V row-sum.  grid = B, block = (64, 8)
// ---------------------------------------------------------------------------
__global__ void vsum_kernel()
{
    __shared__ float sm[8][D_];
    const int b = blockIdx.x;
    const int d = threadIdx.x;       // 0..63
    const int g = threadIdx.y;       // 0..7
    const int chunk = S_ / 8;        // 512

    float s = 0.f;
    const float* base = g_V + ((size_t)b * S_ + (size_t)g * chunk) * D_ + d;
#pragma unroll 4
    for (int r = 0; r < chunk; r++) s += base[(size_t)r * D_];
    sm[g][d] = s;
    __syncthreads();
    if (g == 0) {
        float t = 0.f;
#pragma unroll
        for (int k = 0; k < 8; k++) t += sm[k][d];
        g_Vsum[b * D_ + d] = t;
    }
}

// ---------------------------------------------------------------------------
// Kernel 3: windowed attention combine. One warp per (b, i) position.
// Lane handles dims {lane, lane+32}.
// out[i] = [ e0*Vsum + Σ_w (e_w − e0)·V[j_w] ] / [ Σ_w e_w + e0·(S − n_valid) ]
// with e_w = exp(c_w − m), e0 = exp(−m), m = max(0, max_w c_w).
// ---------------------------------------------------------------------------
__global__ __launch_bounds__(256) void attn_kernel(float* __restrict__ out)
{
    const int gw = (blockIdx.x * blockDim.x + threadIdx.x) >> 5;
    const int lane = threadIdx.x & 31;
    if (gw >= B_ * S_) return;

    const int b = gw >> 12;          // S = 4096
    const int i = gw & (S_ - 1);

    const float* Qr = g_Q + (size_t)gw * D_;
    const float q0 = Qr[lane];
    const float q1 = Qr[lane + 32];

    float c[WIN_];
    bool valid[WIN_];
    int jv[WIN_];
    int nv = 0;
    float cmax = 0.f;   // softmax row includes zeros -> max includes 0

#pragma unroll
    for (int w = 0; w < WIN_; w++) {
        const int j = i + DIL_ * (w - WIN_ / 2);
        jv[w] = j;
        valid[w] = (j >= 0) && (j < S_);
        float p = 0.f;
        if (valid[w]) {
            const float* Kr = g_K + ((size_t)b * S_ + j) * D_;
            p = q0 * Kr[lane] + q1 * Kr[lane + 32];
#pragma unroll
            for (int o = 16; o > 0; o >>= 1)
                p += __shfl_xor_sync(0xffffffffu, p, o);
            nv++;
            cmax = fmaxf(cmax, p);
        }
        c[w] = p;
    }

    const float e0 = expf(-cmax);
    float denom = e0 * (float)(S_ - nv);
    float acc0 = e0 * g_Vsum[b * D_ + lane];
    float acc1 = e0 * g_Vsum[b * D_ + lane + 32];

#pragma unroll
    for (int w = 0; w < WIN_; w++) {
        if (valid[w]) {
            const float ew = expf(c[w] - cmax);
            denom += ew;
            const float f = ew - e0;
            const float* Vr = g_V + ((size_t)b * S_ + jv[w]) * D_;
            acc0 = fmaf(f, Vr[lane], acc0);
            acc1 = fmaf(f, Vr[lane + 32], acc1);
        }
    }

    const float inv = 1.f / denom;
    out[(size_t)gw * D_ + lane] = acc0 * inv;
    out[(size_t)gw * D_ + lane + 32] = acc1 * inv;
}

// ---------------------------------------------------------------------------
extern "C" void kernel_launch(void* const* d_in, const int* in_sizes, int n_in,
                              void* d_out, int out_size)
{
    const float* x  = (const float*)d_in[0];
    const float* Wq = (const float*)d_in[1];
    const float* bq = (const float*)d_in[2];
    const float* Wk = (const float*)d_in[3];
    const float* bk = (const float*)d_in[4];
    const float* Wv = (const float*)d_in[5];
    const float* bv = (const float*)d_in[6];
    float* out = (float*)d_out;

    // 1) QKV projections: grid (8192/64, 3)
    dim3 gg((B_ * S_) / BM, 3);
    qkv_gemm<<<gg, 256>>>(x, Wq, bq, Wk, bk, Wv, bv);

    // 2) per-batch V sum
    vsum_kernel<<<B_, dim3(D_, 8)>>>();

    // 3) windowed softmax combine: one warp per position
    const int warps = B_ * S_;
    attn_kernel<<<(warps * 32 + 255) / 256, 256>>>(out);
}

// round 2
// speedup vs baseline: 1.2467x; 1.2467x over previous
#include <cuda_runtime.h>
#include <math.h>

#define B_ 2
#define S_ 4096
#define E_ 1024
#define D_ 64
#define WIN_ 5
#define DIL_ 2

// Scratch (allocation-free rule: __device__ globals)
__device__ float g_Q[B_ * S_ * D_];
__device__ float g_K[B_ * S_ * D_];
__device__ float g_V[B_ * S_ * D_];
__device__ float g_Vsum[B_ * D_];

// ---------------------------------------------------------------------------
// tf32 helpers
// ---------------------------------------------------------------------------
__device__ __forceinline__ unsigned f2tf32(float f) {
    unsigned r;
    asm("cvt.rna.tf32.f32 %0, %1;" : "=r"(r) : "f"(f));
    return r;
}

__device__ __forceinline__ void mma_tf32(float* c, const unsigned* a, const unsigned* b) {
    asm volatile(
        "mma.sync.aligned.m16n8k8.row.col.f32.tf32.tf32.f32 "
        "{%0,%1,%2,%3}, {%4,%5,%6,%7}, {%8,%9}, {%0,%1,%2,%3};"
        : "+f"(c[0]), "+f"(c[1]), "+f"(c[2]), "+f"(c[3])
        : "r"(a[0]), "r"(a[1]), "r"(a[2]), "r"(a[3]), "r"(b[0]), "r"(b[1]));
}

// ---------------------------------------------------------------------------
// Kernel 1: QKV projection GEMM, 3xTF32 tensor-core path.
// C[8192 x 64] = x[8192 x 1024] @ W[1024 x 64] + bias, W selected by blockIdx.y.
// BM=64, BN=64, BK=16, 128 threads = 4 warps (2x2), warp tile 32x32.
// ---------------------------------------------------------------------------
#define BM 64
#define BN 64
#define BK 16
#define PADA 20   // conflict-free for A fragment loads (verified mod-32)
#define PADB 72   // conflict-free for B fragment loads

__global__ __launch_bounds__(128, 4) void qkv_gemm_tf32(
    const float* __restrict__ x,
    const float* __restrict__ Wq, const float* __restrict__ bq,
    const float* __restrict__ Wk, const float* __restrict__ bk,
    const float* __restrict__ Wv, const float* __restrict__ bv)
{
    const float* W;
    const float* bias;
    float* out;
    if (blockIdx.y == 0)      { W = Wq; bias = bq; out = g_Q; }
    else if (blockIdx.y == 1) { W = Wk; bias = bk; out = g_K; }
    else                      { W = Wv; bias = bv; out = g_V; }

    __shared__ float As_hi[BM][PADA];
    __shared__ float As_lo[BM][PADA];
    __shared__ float Bs_hi[BK][PADB];
    __shared__ float Bs_lo[BK][PADB];

    const int tid  = threadIdx.x;
    const int lane = tid & 31;
    const int wid  = tid >> 5;
    const int wm   = wid >> 1;     // 0..1
    const int wn   = wid & 1;      // 0..1
    const int rowBase = blockIdx.x * BM;

    // global load coordinates
    const int arow = tid >> 2;          // 0..31  (rows arow, arow+32)
    const int ak4  = (tid & 3) * 4;     // 0,4,8,12
    const int bkr  = tid >> 4;          // 0..7   (k rows bkr, bkr+8)
    const int bn4  = (tid & 15) * 4;    // 0..60

    const float* aptr0 = x + (size_t)(rowBase + arow) * E_ + ak4;
    const float* aptr1 = aptr0 + (size_t)32 * E_;
    const float* bptr0 = W + (size_t)bkr * D_ + bn4;
    const float* bptr1 = W + (size_t)(bkr + 8) * D_ + bn4;

    float acc[2][4][4];
#pragma unroll
    for (int mt = 0; mt < 2; mt++)
#pragma unroll
        for (int nt = 0; nt < 4; nt++)
#pragma unroll
            for (int k = 0; k < 4; k++) acc[mt][nt][k] = 0.f;

    float4 pa0, pa1, pb0, pb1;

    // prologue: load tile 0
    pa0 = *(const float4*)(aptr0);
    pa1 = *(const float4*)(aptr1);
    pb0 = *(const float4*)(bptr0);
    pb1 = *(const float4*)(bptr1);

    auto store_tile = [&]() {
        // split A
        float4 h, l;
        h.x = __uint_as_float(f2tf32(pa0.x)); l.x = __uint_as_float(f2tf32(pa0.x - h.x));
        h.y = __uint_as_float(f2tf32(pa0.y)); l.y = __uint_as_float(f2tf32(pa0.y - h.y));
        h.z = __uint_as_float(f2tf32(pa0.z)); l.z = __uint_as_float(f2tf32(pa0.z - h.z));
        h.w = __uint_as_float(f2tf32(pa0.w)); l.w = __uint_as_float(f2tf32(pa0.w - h.w));
        *(float4*)&As_hi[arow][ak4] = h;
        *(float4*)&As_lo[arow][ak4] = l;
        h.x = __uint_as_float(f2tf32(pa1.x)); l.x = __uint_as_float(f2tf32(pa1.x - h.x));
        h.y = __uint_as_float(f2tf32(pa1.y)); l.y = __uint_as_float(f2tf32(pa1.y - h.y));
        h.z = __uint_as_float(f2tf32(pa1.z)); l.z = __uint_as_float(f2tf32(pa1.z - h.z));
        h.w = __uint_as_float(f2tf32(pa1.w)); l.w = __uint_as_float(f2tf32(pa1.w - h.w));
        *(float4*)&As_hi[arow + 32][ak4] = h;
        *(float4*)&As_lo[arow + 32][ak4] = l;
        // split B
        h.x = __uint_as_float(f2tf32(pb0.x)); l.x = __uint_as_float(f2tf32(pb0.x - h.x));
        h.y = __uint_as_float(f2tf32(pb0.y)); l.y = __uint_as_float(f2tf32(pb0.y - h.y));
        h.z = __uint_as_float(f2tf32(pb0.z)); l.z = __uint_as_float(f2tf32(pb0.z - h.z));
        h.w = __uint_as_float(f2tf32(pb0.w)); l.w = __uint_as_float(f2tf32(pb0.w - h.w));
        *(float4*)&Bs_hi[bkr][bn4] = h;
        *(float4*)&Bs_lo[bkr][bn4] = l;
        h.x = __uint_as_float(f2tf32(pb1.x)); l.x = __uint_as_float(f2tf32(pb1.x - h.x));
        h.y = __uint_as_float(f2tf32(pb1.y)); l.y = __uint_as_float(f2tf32(pb1.y - h.y));
        h.z = __uint_as_float(f2tf32(pb1.z)); l.z = __uint_as_float(f2tf32(pb1.z - h.z));
        h.w = __uint_as_float(f2tf32(pb1.w)); l.w = __uint_as_float(f2tf32(pb1.w - h.w));
        *(float4*)&Bs_hi[bkr + 8][bn4] = h;
        *(float4*)&Bs_lo[bkr + 8][bn4] = l;
    };

    auto compute_tile = [&]() {
        const int r  = lane >> 2;
        const int cc = lane & 3;
#pragma unroll
        for (int ks = 0; ks < 2; ks++) {
            const int kb = ks * 8;
            unsigned ah[2][4], al[2][4];
#pragma unroll
            for (int mt = 0; mt < 2; mt++) {
                const int m0 = wm * 32 + mt * 16;
                ah[mt][0] = __float_as_uint(As_hi[m0 + r][kb + cc]);
                ah[mt][1] = __float_as_uint(As_hi[m0 + r + 8][kb + cc]);
                ah[mt][2] = __float_as_uint(As_hi[m0 + r][kb + cc + 4]);
                ah[mt][3] = __float_as_uint(As_hi[m0 + r + 8][kb + cc + 4]);
                al[mt][0] = __float_as_uint(As_lo[m0 + r][kb + cc]);
                al[mt][1] = __float_as_uint(As_lo[m0 + r + 8][kb + cc]);
                al[mt][2] = __float_as_uint(As_lo[m0 + r][kb + cc + 4]);
                al[mt][3] = __float_as_uint(As_lo[m0 + r + 8][kb + cc + 4]);
            }
            unsigned bh[4][2], bl[4][2];
#pragma unroll
            for (int nt = 0; nt < 4; nt++) {
                const int n0 = wn * 32 + nt * 8;
                bh[nt][0] = __float_as_uint(Bs_hi[kb + cc][n0 + r]);
                bh[nt][1] = __float_as_uint(Bs_hi[kb + cc + 4][n0 + r]);
                bl[nt][0] = __float_as_uint(Bs_lo[kb + cc][n0 + r]);
                bl[nt][1] = __float_as_uint(Bs_lo[kb + cc + 4][n0 + r]);
            }
#pragma unroll
            for (int mt = 0; mt < 2; mt++)
#pragma unroll
                for (int nt = 0; nt < 4; nt++) {
                    mma_tf32(acc[mt][nt], ah[mt], bh[nt]);   // hi*hi
                    mma_tf32(acc[mt][nt], al[mt], bh[nt]);   // lo*hi
                    mma_tf32(acc[mt][nt], ah[mt], bl[nt]);   // hi*lo
                }
        }
    };

    store_tile();
    __syncthreads();

    const int KTILES = E_ / BK;   // 64
    for (int kt = 1; kt < KTILES; kt++) {
        // prefetch next tile into registers
        pa0 = *(const float4*)(aptr0 + kt * BK);
        pa1 = *(const float4*)(aptr1 + kt * BK);
        pb0 = *(const float4*)(bptr0 + (size_t)kt * BK * D_);
        pb1 = *(const float4*)(bptr1 + (size_t)kt * BK * D_);

        compute_tile();
        __syncthreads();
        store_tile();
        __syncthreads();
    }
    compute_tile();

    // epilogue: bias + store (float2 per fragment row)
    const int r  = lane >> 2;
    const int cc = lane & 3;
#pragma unroll
    for (int mt = 0; mt < 2; mt++) {
#pragma unroll
        for (int nt = 0; nt < 4; nt++) {
            const int col = wn * 32 + nt * 8 + 2 * cc;
            const float b0v = bias[col];
            const float b1v = bias[col + 1];
            const int row0 = rowBase + wm * 32 + mt * 16 + r;
            float2 v0 = make_float2(acc[mt][nt][0] + b0v, acc[mt][nt][1] + b1v);
            float2 v1 = make_float2(acc[mt][nt][2] + b0v, acc[mt][nt][3] + b1v);
            *(float2*)&out[(size_t)row0 * D_ + col] = v0;
            *(float2*)&out[(size_t)(row0 + 8) * D_ + col] = v1;
        }
    }
}

// ---------------------------------------------------------------------------
// Kernel 2: per-batch V row-sum.  grid = B, block = (64, 8)
// ---------------------------------------------------------------------------
__global__ void vsum_kernel()
{
    __shared__ float sm[8][D_];
    const int b = blockIdx.x;
    const int d = threadIdx.x;
    const int g = threadIdx.y;
    const int chunk = S_ / 8;

    float s = 0.f;
    const float* base = g_V + ((size_t)b * S_ + (size_t)g * chunk) * D_ + d;
#pragma unroll 4
    for (int r = 0; r < chunk; r++) s += base[(size_t)r * D_];
    sm[g][d] = s;
    __syncthreads();
    if (g == 0) {
        float t = 0.f;
#pragma unroll
        for (int k = 0; k < 8; k++) t += sm[k][d];
        g_Vsum[b * D_ + d] = t;
    }
}

// ---------------------------------------------------------------------------
// Kernel 3: windowed attention combine. One warp per (b, i).
// out[i] = [ e0*Vsum + Σ_w (e_w − e0)·V[j_w] ] / [ Σ_w e_w + e0·(S − n_valid) ]
// ---------------------------------------------------------------------------
__global__ __launch_bounds__(256) void attn_kernel(float* __restrict__ out)
{
    const int gw = (blockIdx.x * blockDim.x + threadIdx.x) >> 5;
    const int lane = threadIdx.x & 31;
    if (gw >= B_ * S_) return;

    const int b = gw >> 12;
    const int i = gw & (S_ - 1);

    const float* Qr = g_Q + (size_t)gw * D_;
    const float q0 = Qr[lane];
    const float q1 = Qr[lane + 32];

    float c[WIN_];
    bool valid[WIN_];
    int jv[WIN_];
    int nv = 0;
    float cmax = 0.f;

#pragma unroll
    for (int w = 0; w < WIN_; w++) {
        const int j = i + DIL_ * (w - WIN_ / 2);
        jv[w] = j;
        valid[w] = (j >= 0) && (j < S_);
        float p = 0.f;
        if (valid[w]) {
            const float* Kr = g_K + ((size_t)b * S_ + j) * D_;
            p = q0 * Kr[lane] + q1 * Kr[lane + 32];
#pragma unroll
            for (int o = 16; o > 0; o >>= 1)
                p += __shfl_xor_sync(0xffffffffu, p, o);
            nv++;
            cmax = fmaxf(cmax, p);
        }
        c[w] = p;
    }

    const float e0 = expf(-cmax);
    float denom = e0 * (float)(S_ - nv);
    float acc0 = e0 * g_Vsum[b * D_ + lane];
    float acc1 = e0 * g_Vsum[b * D_ + lane + 32];

#pragma unroll
    for (int w = 0; w < WIN_; w++) {
        if (valid[w]) {
            const float ew = expf(c[w] - cmax);
            denom += ew;
            const float f = ew - e0;
            const float* Vr = g_V + ((size_t)b * S_ + jv[w]) * D_;
            acc0 = fmaf(f, Vr[lane], acc0);
            acc1 = fmaf(f, Vr[lane + 32], acc1);
        }
    }

    const float inv = 1.f / denom;
    out[(size_t)gw * D_ + lane] = acc0 * inv;
    out[(size_t)gw * D_ + lane + 32] = acc1 * inv;
}

// ---------------------------------------------------------------------------
extern "C" void kernel_launch(void* const* d_in, const int* in_sizes, int n_in,
                              void* d_out, int out_size)
{
    const float* x  = (const float*)d_in[0];
    const float* Wq = (const float*)d_in[1];
    const float* bq = (const float*)d_in[2];
    const float* Wk = (const float*)d_in[3];
    const float* bk = (const float*)d_in[4];
    const float* Wv = (const float*)d_in[5];
    const float* bv = (const float*)d_in[6];
    float* out = (float*)d_out;

    dim3 gg((B_ * S_) / BM, 3);
    qkv_gemm_tf32<<<gg, 128>>>(x, Wq, bq, Wk, bk, Wv, bv);

    vsum_kernel<<<B_, dim3(D_, 8)>>>();

    const int warps = B_ * S_;
    attn_kernel<<<(warps * 32 + 255) / 256, 256>>>(out);
}

// round 3
// speedup vs baseline: 1.5159x; 1.2159x over previous
#include <cuda_runtime.h>
#include <math.h>

#define B_ 2
#define S_ 4096
#define E_ 1024
#define D_ 64
#define WIN_ 5
#define DIL_ 2

// Scratch (allocation-free rule: __device__ globals)
__device__ float g_Q[B_ * S_ * D_];
__device__ float g_K[B_ * S_ * D_];
__device__ float g_V[B_ * S_ * D_];
__device__ float g_part[B_ * 16 * D_];   // partial V row-sums

// ---------------------------------------------------------------------------
// tf32 helpers
// ---------------------------------------------------------------------------
__device__ __forceinline__ unsigned f2tf32(float f) {
    unsigned r;
    asm("cvt.rna.tf32.f32 %0, %1;" : "=r"(r) : "f"(f));
    return r;
}

__device__ __forceinline__ void mma_tf32(float* c, const unsigned* a, const unsigned* b) {
    asm volatile(
        "mma.sync.aligned.m16n8k8.row.col.f32.tf32.tf32.f32 "
        "{%0,%1,%2,%3}, {%4,%5,%6,%7}, {%8,%9}, {%0,%1,%2,%3};"
        : "+f"(c[0]), "+f"(c[1]), "+f"(c[2]), "+f"(c[3])
        : "r"(a[0]), "r"(a[1]), "r"(a[2]), "r"(a[3]), "r"(b[0]), "r"(b[1]));
}

// ---------------------------------------------------------------------------
// Kernel 1: QKV projection GEMM, 3xTF32 tensor-core path.
// C[8192 x 64] = x[8192 x 1024] @ W[1024 x 64] + bias, W selected by blockIdx.y.
// BM=64, BN=64, BK=16, 256 threads = 8 warps (4m x 2n), warp tile 16x32.
// Raw fp32 staged in smem; hi/lo tf32 split happens at fragment-load time.
// ---------------------------------------------------------------------------
#define BM 64
#define BN 64
#define BK 16
#define PADA 20   // 64 rows x (16+4): conflict-free for A fragment loads
#define PADB 72   // 16 rows x (64+8): conflict-free for B fragment loads

__global__ __launch_bounds__(256) void qkv_gemm_tf32(
    const float* __restrict__ x,
    const float* __restrict__ Wq, const float* __restrict__ bq,
    const float* __restrict__ Wk, const float* __restrict__ bk,
    const float* __restrict__ Wv, const float* __restrict__ bv)
{
    const float* W;
    const float* bias;
    float* out;
    if (blockIdx.y == 0)      { W = Wq; bias = bq; out = g_Q; }
    else if (blockIdx.y == 1) { W = Wk; bias = bk; out = g_K; }
    else                      { W = Wv; bias = bv; out = g_V; }

    __shared__ float As[BM][PADA];
    __shared__ float Bs[BK][PADB];

    const int tid  = threadIdx.x;
    const int lane = tid & 31;
    const int wid  = tid >> 5;
    const int wm   = wid >> 1;     // 0..3 -> m rows wm*16
    const int wn   = wid & 1;      // 0..1 -> n cols wn*32
    const int rowBase = blockIdx.x * BM;

    // global load coordinates: 256 threads, 1 float4 each for A and B
    const int arow = tid >> 2;          // 0..63
    const int ak4  = (tid & 3) * 4;     // 0,4,8,12
    const int bkr  = tid >> 4;          // 0..15
    const int bn4  = (tid & 15) * 4;    // 0..60

    const float* aptr = x + (size_t)(rowBase + arow) * E_ + ak4;
    const float* bptr = W + (size_t)bkr * D_ + bn4;

    float acc[4][4];
#pragma unroll
    for (int nt = 0; nt < 4; nt++)
#pragma unroll
        for (int k = 0; k < 4; k++) acc[nt][k] = 0.f;

    float4 pa, pb;

    // prologue: load tile 0
    pa = *(const float4*)(aptr);
    pb = *(const float4*)(bptr);

    const int r  = lane >> 2;
    const int cc = lane & 3;
    const int m0 = wm * 16;

    auto compute_tile = [&]() {
#pragma unroll
        for (int ks = 0; ks < 2; ks++) {
            const int kb = ks * 8;
            // A fragment (m16k8): raw loads + hi/lo split
            float ar[4];
            ar[0] = As[m0 + r][kb + cc];
            ar[1] = As[m0 + r + 8][kb + cc];
            ar[2] = As[m0 + r][kb + cc + 4];
            ar[3] = As[m0 + r + 8][kb + cc + 4];
            unsigned ah[4], al[4];
#pragma unroll
            for (int i = 0; i < 4; i++) {
                ah[i] = f2tf32(ar[i]);
                al[i] = f2tf32(ar[i] - __uint_as_float(ah[i]));
            }
            // B fragments (k8n8 x 4)
            unsigned bh[4][2], bl[4][2];
#pragma unroll
            for (int nt = 0; nt < 4; nt++) {
                const int n0 = wn * 32 + nt * 8;
                float b0 = Bs[kb + cc][n0 + r];
                float b1 = Bs[kb + cc + 4][n0 + r];
                bh[nt][0] = f2tf32(b0);
                bl[nt][0] = f2tf32(b0 - __uint_as_float(bh[nt][0]));
                bh[nt][1] = f2tf32(b1);
                bl[nt][1] = f2tf32(b1 - __uint_as_float(bh[nt][1]));
            }
#pragma unroll
            for (int nt = 0; nt < 4; nt++) {
                mma_tf32(acc[nt], ah, bh[nt]);   // hi*hi
                mma_tf32(acc[nt], al, bh[nt]);   // lo*hi
                mma_tf32(acc[nt], ah, bl[nt]);   // hi*lo
            }
        }
    };

    // store tile 0
    *(float4*)&As[arow][ak4] = pa;
    *(float4*)&Bs[bkr][bn4] = pb;
    __syncthreads();

    const int KTILES = E_ / BK;   // 64
    for (int kt = 1; kt < KTILES; kt++) {
        // prefetch next tile into registers
        pa = *(const float4*)(aptr + kt * BK);
        pb = *(const float4*)(bptr + (size_t)kt * BK * D_);

        compute_tile();
        __syncthreads();
        *(float4*)&As[arow][ak4] = pa;
        *(float4*)&Bs[bkr][bn4] = pb;
        __syncthreads();
    }
    compute_tile();

    // epilogue: bias + store (float2 per fragment row)
#pragma unroll
    for (int nt = 0; nt < 4; nt++) {
        const int col = wn * 32 + nt * 8 + 2 * cc;
        const float b0v = bias[col];
        const float b1v = bias[col + 1];
        const int row0 = rowBase + m0 + r;
        float2 v0 = make_float2(acc[nt][0] + b0v, acc[nt][1] + b1v);
        float2 v1 = make_float2(acc[nt][2] + b0v, acc[nt][3] + b1v);
        *(float2*)&out[(size_t)row0 * D_ + col] = v0;
        *(float2*)&out[(size_t)(row0 + 8) * D_ + col] = v1;
    }
}

// ---------------------------------------------------------------------------
// Kernel 2: per-batch partial V row-sums. grid = B*16, block = (64, 4).
// Block p of batch b sums rows [p*256, (p+1)*256) into g_part[b][p][:].
// ---------------------------------------------------------------------------
__global__ void vsum_partial()
{
    __shared__ float sm[4][D_];
    const int b = blockIdx.x >> 4;
    const int p = blockIdx.x & 15;
    const int d = threadIdx.x;       // 0..63
    const int g = threadIdx.y;       // 0..3

    float s = 0.f;
    const float* base = g_V + ((size_t)b * S_ + (size_t)p * 256 + g) * D_ + d;
#pragma unroll 8
    for (int rr = 0; rr < 64; rr++) s += base[(size_t)rr * 4 * D_];
    sm[g][d] = s;
    __syncthreads();
    if (g == 0) {
        float t = sm[0][d] + sm[1][d] + sm[2][d] + sm[3][d];
        g_part[(b * 16 + p) * D_ + d] = t;
    }
}

// ---------------------------------------------------------------------------
// Kernel 3: windowed attention combine. One warp per (b, i).
// out[i] = [ e0*Vsum + sum_w (e_w - e0)*V[j_w] ] / [ sum_w e_w + e0*(S - n_valid) ]
// Vsum reduced on the fly from the 16 partials (L1/L2-resident, 8KB total).
// ---------------------------------------------------------------------------
__global__ __launch_bounds__(256) void attn_kernel(float* __restrict__ out)
{
    const int gw = (blockIdx.x * blockDim.x + threadIdx.x) >> 5;
    const int lane = threadIdx.x & 31;
    if (gw >= B_ * S_) return;

    const int b = gw >> 12;
    const int i = gw & (S_ - 1);

    const float* Qr = g_Q + (size_t)gw * D_;
    const float q0 = Qr[lane];
    const float q1 = Qr[lane + 32];

    float c[WIN_];
    bool valid[WIN_];
    int jv[WIN_];
    int nv = 0;
    float cmax = 0.f;   // softmax row includes zeros -> max includes 0

#pragma unroll
    for (int w = 0; w < WIN_; w++) {
        const int j = i + DIL_ * (w - WIN_ / 2);
        jv[w] = j;
        valid[w] = (j >= 0) && (j < S_);
        float p = 0.f;
        if (valid[w]) {
            const float* Kr = g_K + ((size_t)b * S_ + j) * D_;
            p = q0 * Kr[lane] + q1 * Kr[lane + 32];
#pragma unroll
            for (int o = 16; o > 0; o >>= 1)
                p += __shfl_xor_sync(0xffffffffu, p, o);
            nv++;
            cmax = fmaxf(cmax, p);
        }
        c[w] = p;
    }

    // on-the-fly Vsum from 16 partials
    float vs0 = 0.f, vs1 = 0.f;
    const float* pp = g_part + b * 16 * D_;
#pragma unroll
    for (int p = 0; p < 16; p++) {
        vs0 += pp[p * D_ + lane];
        vs1 += pp[p * D_ + lane + 32];
    }

    const float e0 = expf(-cmax);
    float denom = e0 * (float)(S_ - nv);
    float acc0 = e0 * vs0;
    float acc1 = e0 * vs1;

#pragma unroll
    for (int w = 0; w < WIN_; w++) {
        if (valid[w]) {
            const float ew = expf(c[w] - cmax);
            denom += ew;
            const float f = ew - e0;
            const float* Vr = g_V + ((size_t)b * S_ + jv[w]) * D_;
            acc0 = fmaf(f, Vr[lane], acc0);
            acc1 = fmaf(f, Vr[lane + 32], acc1);
        }
    }

    const float inv = 1.f / denom;
    out[(size_t)gw * D_ + lane] = acc0 * inv;
    out[(size_t)gw * D_ + lane + 32] = acc1 * inv;
}

// ---------------------------------------------------------------------------
extern "C" void kernel_launch(void* const* d_in, const int* in_sizes, int n_in,
                              void* d_out, int out_size)
{
    const float* x  = (const float*)d_in[0];
    const float* Wq = (const float*)d_in[1];
    const float* bq = (const float*)d_in[2];
    const float* Wk = (const float*)d_in[3];
    const float* bk = (const float*)d_in[4];
    const float* Wv = (const float*)d_in[5];
    const float* bv = (const float*)d_in[6];
    float* out = (float*)d_out;

    dim3 gg((B_ * S_) / BM, 3);
    qkv_gemm_tf32<<<gg, 256>>>(x, Wq, bq, Wk, bk, Wv, bv);

    vsum_partial<<<B_ * 16, dim3(D_, 4)>>>();

    const int warps = B_ * S_;
    attn_kernel<<<(warps * 32 + 255) / 256, 256>>>(out);
}